// round 13
// baseline (speedup 1.0000x reference)
#include <cuda_runtime.h>
#include <cuda_fp16.h>
#include <cstdint>

// ============================================================================
// FeatureSharingLayer: 5 chained 128x128 GEMMs over M = 262144 rows.
// mma.sync m16n8k16 fp16 (fp32 accum). Warp-level DUAL-TILE: each warp owns
// 32 rows, so every B-fragment LDS.128 feeds 4 MMAs -> smem crossbar bytes
// per row halved (crossbar was co-saturated with tensor at 53%/53%).
// Register discipline: B p-loop unroll 2, tf residual added at store time,
// residual A parked in warp-private smem. Target <=240 regs, no spill.
// ============================================================================

#define DIM 128
#define M_TOTAL (32768 * 8)        // 262144
#define N_BLK32 (M_TOTAL / 32)     // 8192 32-row blocks
#define N_STAGES 5
#define GRID_MAIN 152
#define THREADS 256
#define N_WARPS (THREADS / 32)     // 8
#define STRIDE (GRID_MAIN * N_WARPS)

// packed B fragments: [stage][kb(8)][nbp(8)][lane(32)] -> uint4
__device__ uint4 g_fragB[N_STAGES * 8 * 8 * 32];
__device__ float g_bias[N_STAGES][DIM];

#define SMEM_FRAG_BYTES (N_STAGES * 8 * 8 * 32 * 16)      // 163840
#define SMEM_BIAS_BYTES (N_STAGES * DIM * 4)              // 2560
#define SMEM_RES_BYTES  (N_WARPS * 2 * 16 * 32 * 8)       // 65536
#define SMEM_TOTAL (SMEM_FRAG_BYTES + SMEM_BIAS_BYTES + SMEM_RES_BYTES) // 231936

// ----------------------------------------------------------------------------
// Prologue: fold weights, convert fp16, scatter into B-fragment layout.
// ----------------------------------------------------------------------------
__global__ void precompute_pack(
    const float* __restrict__ ipw, const float* __restrict__ ipb,
    const float* __restrict__ ow,  const float* __restrict__ ob,
    const float* __restrict__ fw1, const float* __restrict__ fb1,
    const float* __restrict__ fw2, const float* __restrict__ fb2,
    const float* __restrict__ uw1, const float* __restrict__ ub1,
    const float* __restrict__ uw2, const float* __restrict__ ub2)
{
    const int n = blockIdx.x, s = blockIdx.y, k = threadIdx.x;
    __shared__ float srow[DIM];

    float v = 0.f;
    if (s == 0) {
        srow[k] = ow[n * DIM + k];
        __syncthreads();
#pragma unroll 8
        for (int j = 0; j < DIM; j++)
            v += srow[j] * ipw[(256 + j) * DIM + k];
    } else if (s == 1) {
#pragma unroll
        for (int t = 0; t < 8; t++) v += fw1[n * 1024 + t * DIM + k];
    } else if (s == 2) v = fw2[n * DIM + k];
    else if (s == 3)   v = uw1[n * DIM + k];
    else               v = uw2[n * DIM + k];

    {
        const int lane = (n & 7) * 4 + ((k & 7) >> 1);
        const int idx4 = ((s * 8 + (k >> 4)) * 8 + (n >> 4)) * 32 + lane;
        const int slot = ((n >> 3) & 1) * 4 + ((k >> 3) & 1) * 2 + (k & 1);
        reinterpret_cast<__half*>(g_fragB)[idx4 * 8 + slot] = __float2half(v);
    }

    if (k == 0) {
        float b;
        if (s == 0) {
            b = ob[n];
            for (int j = 0; j < DIM; j++) b += ow[n * DIM + j] * ipb[256 + j];
        } else if (s == 1) b = fb1[n];
        else if (s == 2)   b = fb2[n];
        else if (s == 3)   b = ub1[n];
        else               b = ub2[n];
        g_bias[s][n] = b;
    }
}

// ----------------------------------------------------------------------------
// Device helpers
// ----------------------------------------------------------------------------
__device__ __forceinline__ unsigned pack_h2(float x, float y)
{
    __half2 h = __floats2half2_rn(x, y);
    return *reinterpret_cast<unsigned*>(&h);
}

__device__ __forceinline__ void mma16816(float c[4], const unsigned a[4],
                                         unsigned b0, unsigned b1)
{
    asm volatile(
        "mma.sync.aligned.m16n8k16.row.col.f32.f16.f16.f32 "
        "{%0,%1,%2,%3}, {%4,%5,%6,%7}, {%8,%9}, {%0,%1,%2,%3};\n"
        : "+f"(c[0]), "+f"(c[1]), "+f"(c[2]), "+f"(c[3])
        : "r"(a[0]), "r"(a[1]), "r"(a[2]), "r"(a[3]), "r"(b0), "r"(b1));
}

// dual-tile GEMM: one B uint4 feeds 4 MMAs. p-loop unroll 2 keeps only
// 2 uint4 B-temps (8 regs) in flight -> bounded register pressure.
__device__ __forceinline__ void run_gemm2(const uint4* __restrict__ sFrag, int s,
                                          int lane,
                                          const unsigned a0[8][4],
                                          const unsigned a1[8][4],
                                          float c0[16][4], float c1[16][4])
{
#pragma unroll
    for (int kb = 0; kb < 8; kb++) {
        const uint4* bp = sFrag + ((s * 8 + kb) * 8) * 32 + lane;
#pragma unroll 2
        for (int p = 0; p < 8; p++) {
            uint4 b = bp[p * 32];
            mma16816(c0[2 * p],     a0[kb], b.x, b.y);
            mma16816(c0[2 * p + 1], a0[kb], b.z, b.w);
            mma16816(c1[2 * p],     a1[kb], b.x, b.y);
            mma16816(c1[2 * p + 1], a1[kb], b.z, b.w);
        }
    }
}

__device__ __forceinline__ void bias_init(const float* __restrict__ sb, int s,
                                          int t, float c[16][4])
{
    const float2* bp = reinterpret_cast<const float2*>(sb + s * DIM + 2 * t);
#pragma unroll
    for (int nb = 0; nb < 16; nb++) {
        float2 b = bp[nb * 4];
        c[nb][0] = b.x; c[nb][1] = b.y; c[nb][2] = b.x; c[nb][3] = b.y;
    }
}

__device__ __forceinline__ void do_relu(float c[16][4])
{
#pragma unroll
    for (int nb = 0; nb < 16; nb++) {
        c[nb][0] = fmaxf(c[nb][0], 0.f); c[nb][1] = fmaxf(c[nb][1], 0.f);
        c[nb][2] = fmaxf(c[nb][2], 0.f); c[nb][3] = fmaxf(c[nb][3], 0.f);
    }
}

__device__ __forceinline__ void acc_to_afrag(const float c[16][4], unsigned a[8][4])
{
#pragma unroll
    for (int kb = 0; kb < 8; kb++) {
        a[kb][0] = pack_h2(c[2 * kb][0],     c[2 * kb][1]);
        a[kb][1] = pack_h2(c[2 * kb][2],     c[2 * kb][3]);
        a[kb][2] = pack_h2(c[2 * kb + 1][0], c[2 * kb + 1][1]);
        a[kb][3] = pack_h2(c[2 * kb + 1][2], c[2 * kb + 1][3]);
    }
}

// warp-private fp16 residual in smem (fragment-native, conflict-free)
__device__ __forceinline__ void store_res(uint2* __restrict__ sResW, int lane,
                                          const float c[16][4])
{
    uint2* p = sResW + lane;
#pragma unroll
    for (int nb = 0; nb < 16; nb++)
        p[nb * 32] = make_uint2(pack_h2(c[nb][0], c[nb][1]),
                                pack_h2(c[nb][2], c[nb][3]));
}

__device__ __forceinline__ void init_from_res(const uint2* __restrict__ sResW,
                                              int lane,
                                              const float* __restrict__ sb, int s,
                                              int t, float c[16][4])
{
    const uint2* p = sResW + lane;
    const float2* bp = reinterpret_cast<const float2*>(sb + s * DIM + 2 * t);
#pragma unroll
    for (int nb = 0; nb < 16; nb++) {
        uint2 r = p[nb * 32];
        float2 b = bp[nb * 4];
        float2 f0 = __half22float2(*reinterpret_cast<__half2*>(&r.x));
        float2 f1 = __half22float2(*reinterpret_cast<__half2*>(&r.y));
        c[nb][0] = b.x + f0.x; c[nb][1] = b.y + f0.y;
        c[nb][2] = b.x + f1.x; c[nb][3] = b.y + f1.y;
    }
}

// load 16 rows of tf as stage-0 A fragments
__device__ __forceinline__ void load_afrag_gmem(const float* __restrict__ p0,
                                                int t, unsigned a[8][4])
{
    const float* p1 = p0 + 8 * DIM;
#pragma unroll
    for (int kb = 0; kb < 8; kb++) {
        float2 x0 = *reinterpret_cast<const float2*>(p0 + kb * 16 + 2 * t);
        float2 x1 = *reinterpret_cast<const float2*>(p1 + kb * 16 + 2 * t);
        float2 x2 = *reinterpret_cast<const float2*>(p0 + kb * 16 + 8 + 2 * t);
        float2 x3 = *reinterpret_cast<const float2*>(p1 + kb * 16 + 8 + 2 * t);
        a[kb][0] = pack_h2(x0.x, x0.y);
        a[kb][1] = pack_h2(x1.x, x1.y);
        a[kb][2] = pack_h2(x2.x, x2.y);
        a[kb][3] = pack_h2(x3.x, x3.y);
    }
}

// store 16 rows: out = acc + tf (residual + store, tiny live window)
__device__ __forceinline__ void store_out(float* __restrict__ o0,
                                          const float* __restrict__ p0,
                                          int t, const float c[16][4])
{
    const float* p1 = p0 + 8 * DIM;
    float* o1 = o0 + 8 * DIM;
#pragma unroll
    for (int nb = 0; nb < 16; nb++) {
        float2 q0 = *reinterpret_cast<const float2*>(p0 + nb * 8 + 2 * t);
        float2 q1 = *reinterpret_cast<const float2*>(p1 + nb * 8 + 2 * t);
        *reinterpret_cast<float2*>(o0 + nb * 8 + 2 * t) =
            make_float2(c[nb][0] + q0.x, c[nb][1] + q0.y);
        *reinterpret_cast<float2*>(o1 + nb * 8 + 2 * t) =
            make_float2(c[nb][2] + q1.x, c[nb][3] + q1.y);
    }
}

// ----------------------------------------------------------------------------
// Main fused kernel: persistent, warp-independent, 32 rows per warp-iteration.
// ----------------------------------------------------------------------------
__global__ void __launch_bounds__(THREADS, 1)
fused_kernel(const float* __restrict__ tf, float* __restrict__ out)
{
    extern __shared__ unsigned char smem[];
    uint4* sFrag = reinterpret_cast<uint4*>(smem);
    float* sBias = reinterpret_cast<float*>(smem + SMEM_FRAG_BYTES);
    uint2* sRes  = reinterpret_cast<uint2*>(smem + SMEM_FRAG_BYTES + SMEM_BIAS_BYTES);

    {   // one-time weight staging
        const uint4* src = g_fragB;
        for (int i = threadIdx.x; i < SMEM_FRAG_BYTES / 16; i += THREADS)
            sFrag[i] = src[i];
        const float* bs = &g_bias[0][0];
        for (int i = threadIdx.x; i < N_STAGES * DIM; i += THREADS)
            sBias[i] = bs[i];
    }
    __syncthreads();

    const int warp = threadIdx.x >> 5, lane = threadIdx.x & 31;
    const int g = lane >> 2, t = lane & 3;
    uint2* sResW = sRes + warp * (2 * 16 * 32);

#pragma unroll 1
    for (int blk = blockIdx.x * N_WARPS + warp; blk < N_BLK32; blk += STRIDE) {
        const float* p0a = tf + (size_t)(blk * 32 + g) * DIM;   // tile a rows
        const float* p0b = p0a + 16 * DIM;                      // tile b rows

        unsigned frX0[8][4], frX1[8][4];
        load_afrag_gmem(p0a, t, frX0);
        load_afrag_gmem(p0b, t, frX1);

        float acc0[16][4], acc1[16][4];

        // ---- S0: A = tf @ Wc^T + bc ----
        bias_init(sBias, 0, t, acc0);
        bias_init(sBias, 0, t, acc1);
        run_gemm2(sFrag, 0, lane, frX0, frX1, acc0, acc1);
        store_res(sResW,            lane, acc0);     // park A (fp16) in smem
        store_res(sResW + 16 * 32,  lane, acc1);
        acc_to_afrag(acc0, frX0);                    // frX := A
        acc_to_afrag(acc1, frX1);

        // ---- S1: h = relu(A @ W1eff^T + b1) ----
        bias_init(sBias, 1, t, acc0);
        bias_init(sBias, 1, t, acc1);
        run_gemm2(sFrag, 1, lane, frX0, frX1, acc0, acc1);
        do_relu(acc0); do_relu(acc1);
        acc_to_afrag(acc0, frX0);                    // frX := h
        acc_to_afrag(acc1, frX1);

        // ---- S2: Ahat = h @ W2^T + b2 + A (A from smem) ----
        init_from_res(sResW,           lane, sBias, 2, t, acc0);
        init_from_res(sResW + 16 * 32, lane, sBias, 2, t, acc1);
        run_gemm2(sFrag, 2, lane, frX0, frX1, acc0, acc1);
        acc_to_afrag(acc0, frX0);                    // frX := Ahat
        acc_to_afrag(acc1, frX1);

        // ---- S3: h2 = relu(Ahat @ W3^T + b3) ----
        bias_init(sBias, 3, t, acc0);
        bias_init(sBias, 3, t, acc1);
        run_gemm2(sFrag, 3, lane, frX0, frX1, acc0, acc1);
        do_relu(acc0); do_relu(acc1);
        acc_to_afrag(acc0, frX0);                    // frX := h2
        acc_to_afrag(acc1, frX1);

        // ---- S4: out = h2 @ W4^T + b4 (+ tf at store) ----
        bias_init(sBias, 4, t, acc0);
        bias_init(sBias, 4, t, acc1);
        run_gemm2(sFrag, 4, lane, frX0, frX1, acc0, acc1);

        float* o0a = out + (size_t)(blk * 32 + g) * DIM;
        store_out(o0a,            p0a, t, acc0);
        store_out(o0a + 16 * DIM, p0b, t, acc1);
    }
}

// ----------------------------------------------------------------------------
extern "C" void kernel_launch(void* const* d_in, const int* in_sizes, int n_in,
                              void* d_out, int out_size)
{
    const float* tf  = (const float*)d_in[0];
    const float* ipw = (const float*)d_in[1];
    const float* ipb = (const float*)d_in[2];
    const float* ow  = (const float*)d_in[3];
    const float* ob  = (const float*)d_in[4];
    const float* fw1 = (const float*)d_in[5];
    const float* fb1 = (const float*)d_in[6];
    const float* fw2 = (const float*)d_in[7];
    const float* fb2 = (const float*)d_in[8];
    const float* uw1 = (const float*)d_in[9];
    const float* ub1 = (const float*)d_in[10];
    const float* uw2 = (const float*)d_in[11];
    const float* ub2 = (const float*)d_in[12];

    precompute_pack<<<dim3(128, 5), 128>>>(ipw, ipb, ow, ob, fw1, fb1,
                                           fw2, fb2, uw1, ub1, uw2, ub2);

    cudaFuncSetAttribute(fused_kernel,
                         cudaFuncAttributeMaxDynamicSharedMemorySize, SMEM_TOTAL);
    fused_kernel<<<GRID_MAIN, THREADS, SMEM_TOTAL>>>(tf, (float*)d_out);
}

// round 15
// speedup vs baseline: 6.5977x; 6.5977x over previous
#include <cuda_runtime.h>
#include <cuda_fp16.h>
#include <cstdint>

// ============================================================================
// FeatureSharingLayer: 5 chained 128x128 GEMMs over M = 262144 rows.
// mma.sync m16n8k16 fp16 (fp32 accum), warp-independent 16-row blocks.
// R15: coalesced gmem I/O through a 4KB warp-private swizzled smem bounce.
//  - input: 16x LDG.128 full fp32 rows -> fp16 -> bounce (swizzle granule 16B)
//  - tf stays in bounce until S4 residual (fp16, no gmem re-read)
//  - output: bounce becomes fp32 row buffer after S4; drained with row STG.128
// GEMM core identical to R11 (168 regs, no spill).
// Swizzle: off(r, cbytes) = r*PITCH + (cbytes ^ ((r&7)<<4)).
// ============================================================================

#define DIM 128
#define M_TOTAL (32768 * 8)        // 262144
#define N_BLK16 (M_TOTAL / 16)     // 16384
#define N_STAGES 5
#define GRID_MAIN 152
#define THREADS 256
#define N_WARPS (THREADS / 32)     // 8
#define STRIDE (GRID_MAIN * N_WARPS)

// packed B fragments: [stage][kb(8)][nbp(8)][lane(32)] -> uint4
__device__ uint4 g_fragB[N_STAGES * 8 * 8 * 32];
__device__ float g_bias[N_STAGES][DIM];

// smem layout
#define SMEM_FRAG_BYTES (N_STAGES * 8 * 8 * 32 * 16)       // 163840
#define SMEM_BIAS_OFF   SMEM_FRAG_BYTES
#define SMEM_BIAS_BYTES (N_STAGES * DIM * 4)               // 2560
#define SMEM_RESA_OFF   (SMEM_BIAS_OFF + SMEM_BIAS_BYTES)  // 166400
#define SMEM_RESA_BYTES (N_WARPS * 4096)                   // 32768
#define SMEM_IO_OFF     (SMEM_RESA_OFF + SMEM_RESA_BYTES)  // 199168
#define SMEM_IO_BYTES   (N_WARPS * 4096)                   // 32768
#define SMEM_TOTAL      (SMEM_IO_OFF + SMEM_IO_BYTES)      // 231936

// ----------------------------------------------------------------------------
// Prologue: fold weights, convert fp16, scatter into B-fragment layout.
// ----------------------------------------------------------------------------
__global__ void precompute_pack(
    const float* __restrict__ ipw, const float* __restrict__ ipb,
    const float* __restrict__ ow,  const float* __restrict__ ob,
    const float* __restrict__ fw1, const float* __restrict__ fb1,
    const float* __restrict__ fw2, const float* __restrict__ fb2,
    const float* __restrict__ uw1, const float* __restrict__ ub1,
    const float* __restrict__ uw2, const float* __restrict__ ub2)
{
    const int n = blockIdx.x, s = blockIdx.y, k = threadIdx.x;
    __shared__ float srow[DIM];

    float v = 0.f;
    if (s == 0) {
        srow[k] = ow[n * DIM + k];
        __syncthreads();
#pragma unroll 8
        for (int j = 0; j < DIM; j++)
            v += srow[j] * ipw[(256 + j) * DIM + k];
    } else if (s == 1) {
#pragma unroll
        for (int t = 0; t < 8; t++) v += fw1[n * 1024 + t * DIM + k];
    } else if (s == 2) v = fw2[n * DIM + k];
    else if (s == 3)   v = uw1[n * DIM + k];
    else               v = uw2[n * DIM + k];

    {
        const int lane = (n & 7) * 4 + ((k & 7) >> 1);
        const int idx4 = ((s * 8 + (k >> 4)) * 8 + (n >> 4)) * 32 + lane;
        const int slot = ((n >> 3) & 1) * 4 + ((k >> 3) & 1) * 2 + (k & 1);
        reinterpret_cast<__half*>(g_fragB)[idx4 * 8 + slot] = __float2half(v);
    }

    if (k == 0) {
        float b;
        if (s == 0) {
            b = ob[n];
            for (int j = 0; j < DIM; j++) b += ow[n * DIM + j] * ipb[256 + j];
        } else if (s == 1) b = fb1[n];
        else if (s == 2)   b = fb2[n];
        else if (s == 3)   b = ub1[n];
        else               b = ub2[n];
        g_bias[s][n] = b;
    }
}

// ----------------------------------------------------------------------------
// Device helpers
// ----------------------------------------------------------------------------
__device__ __forceinline__ unsigned pack_h2(float x, float y)
{
    __half2 h = __floats2half2_rn(x, y);
    return *reinterpret_cast<unsigned*>(&h);
}

__device__ __forceinline__ void mma16816(float c[4], const unsigned a[4],
                                         unsigned b0, unsigned b1)
{
    asm volatile(
        "mma.sync.aligned.m16n8k16.row.col.f32.f16.f16.f32 "
        "{%0,%1,%2,%3}, {%4,%5,%6,%7}, {%8,%9}, {%0,%1,%2,%3};\n"
        : "+f"(c[0]), "+f"(c[1]), "+f"(c[2]), "+f"(c[3])
        : "r"(a[0]), "r"(a[1]), "r"(a[2]), "r"(a[3]), "r"(b0), "r"(b1));
}

__device__ __forceinline__ void run_gemm(const uint4* __restrict__ sFrag, int s,
                                         int lane, const unsigned a[8][4],
                                         float c[16][4])
{
#pragma unroll
    for (int kb = 0; kb < 8; kb++) {
        const uint4* bp = sFrag + ((s * 8 + kb) * 8) * 32 + lane;
#pragma unroll
        for (int p = 0; p < 8; p++) {
            uint4 b = bp[p * 32];
            mma16816(c[2 * p],     a[kb], b.x, b.y);
            mma16816(c[2 * p + 1], a[kb], b.z, b.w);
        }
    }
}

__device__ __forceinline__ void bias_init(const float* __restrict__ sb, int s,
                                          int t, float c[16][4])
{
    const float2* bp = reinterpret_cast<const float2*>(sb + s * DIM + 2 * t);
#pragma unroll
    for (int nb = 0; nb < 16; nb++) {
        float2 b = bp[nb * 4];
        c[nb][0] = b.x; c[nb][1] = b.y; c[nb][2] = b.x; c[nb][3] = b.y;
    }
}

__device__ __forceinline__ void do_relu(float c[16][4])
{
#pragma unroll
    for (int nb = 0; nb < 16; nb++) {
        c[nb][0] = fmaxf(c[nb][0], 0.f); c[nb][1] = fmaxf(c[nb][1], 0.f);
        c[nb][2] = fmaxf(c[nb][2], 0.f); c[nb][3] = fmaxf(c[nb][3], 0.f);
    }
}

__device__ __forceinline__ void acc_to_afrag(const float c[16][4], unsigned a[8][4])
{
#pragma unroll
    for (int kb = 0; kb < 8; kb++) {
        a[kb][0] = pack_h2(c[2 * kb][0],     c[2 * kb][1]);
        a[kb][1] = pack_h2(c[2 * kb][2],     c[2 * kb][3]);
        a[kb][2] = pack_h2(c[2 * kb + 1][0], c[2 * kb + 1][1]);
        a[kb][3] = pack_h2(c[2 * kb + 1][2], c[2 * kb + 1][3]);
    }
}

// warp-private fp16 residual-A in smem (fragment-native, conflict-free)
__device__ __forceinline__ void store_res(uint2* __restrict__ sResW, int lane,
                                          const float c[16][4])
{
    uint2* p = sResW + lane;
#pragma unroll
    for (int nb = 0; nb < 16; nb++)
        p[nb * 32] = make_uint2(pack_h2(c[nb][0], c[nb][1]),
                                pack_h2(c[nb][2], c[nb][3]));
}

__device__ __forceinline__ void init_from_res(const uint2* __restrict__ sResW,
                                              int lane,
                                              const float* __restrict__ sb, int s,
                                              int t, float c[16][4])
{
    const uint2* p = sResW + lane;
    const float2* bp = reinterpret_cast<const float2*>(sb + s * DIM + 2 * t);
#pragma unroll
    for (int nb = 0; nb < 16; nb++) {
        uint2 r = p[nb * 32];
        float2 b = bp[nb * 4];
        float2 f0 = __half22float2(*reinterpret_cast<__half2*>(&r.x));
        float2 f1 = __half22float2(*reinterpret_cast<__half2*>(&r.y));
        c[nb][0] = b.x + f0.x; c[nb][1] = b.y + f0.y;
        c[nb][2] = b.x + f1.x; c[nb][3] = b.y + f1.y;
    }
}

// swizzled offset inside the 4KB IO bounce: row r (0..15), byte column c
__device__ __forceinline__ int io_off(int r, int c)
{
    return r * 256 + (c ^ ((r & 7) << 4));
}

// ----------------------------------------------------------------------------
// Main fused kernel: persistent, warp-independent, coalesced I/O
// ----------------------------------------------------------------------------
__global__ void __launch_bounds__(THREADS, 1)
fused_kernel(const float* __restrict__ tf, float* __restrict__ out)
{
    extern __shared__ unsigned char smem[];
    uint4* sFrag = reinterpret_cast<uint4*>(smem);
    float* sBias = reinterpret_cast<float*>(smem + SMEM_BIAS_OFF);

    {   // one-time weight staging
        const uint4* src = g_fragB;
        for (int i = threadIdx.x; i < SMEM_FRAG_BYTES / 16; i += THREADS)
            sFrag[i] = src[i];
        const float* bs = &g_bias[0][0];
        for (int i = threadIdx.x; i < N_STAGES * DIM; i += THREADS)
            sBias[i] = bs[i];
    }
    __syncthreads();

    const int warp = threadIdx.x >> 5, lane = threadIdx.x & 31;
    const int g = lane >> 2, t = lane & 3;

    uint2*         sResW = reinterpret_cast<uint2*>(smem + SMEM_RESA_OFF) + warp * 512;
    unsigned char* sIOW  = smem + SMEM_IO_OFF + warp * 4096;

#pragma unroll 1
    for (int blk = blockIdx.x * N_WARPS + warp; blk < N_BLK16; blk += STRIDE) {
        const int base = blk * 16;

        // ---- input: coalesced fp32 rows -> fp16 swizzled bounce ----
#pragma unroll 4
        for (int r = 0; r < 16; r++) {
            float4 v = *reinterpret_cast<const float4*>(
                tf + (size_t)(base + r) * DIM + lane * 4);
            *reinterpret_cast<uint2*>(sIOW + io_off(r, lane * 8)) =
                make_uint2(pack_h2(v.x, v.y), pack_h2(v.z, v.w));
        }
        __syncwarp();

        // ---- stage-0 A fragments from bounce (conflict-free via swizzle) ----
        unsigned frX[8][4];
#pragma unroll
        for (int kb = 0; kb < 8; kb++) {
            frX[kb][0] = *reinterpret_cast<unsigned*>(sIOW + io_off(g,     kb * 32 + 4 * t));
            frX[kb][1] = *reinterpret_cast<unsigned*>(sIOW + io_off(g + 8, kb * 32 + 4 * t));
            frX[kb][2] = *reinterpret_cast<unsigned*>(sIOW + io_off(g,     kb * 32 + 16 + 4 * t));
            frX[kb][3] = *reinterpret_cast<unsigned*>(sIOW + io_off(g + 8, kb * 32 + 16 + 4 * t));
        }

        float acc[16][4];

        // ---- S0: A = tf @ Wc^T + bc ----
        bias_init(sBias, 0, t, acc);
        run_gemm(sFrag, 0, lane, frX, acc);
        store_res(sResW, lane, acc);                 // park A (fp16)
        acc_to_afrag(acc, frX);                      // frX := A

        // ---- S1: h = relu(A @ W1eff^T + b1) ----
        bias_init(sBias, 1, t, acc);
        run_gemm(sFrag, 1, lane, frX, acc);
        do_relu(acc);
        acc_to_afrag(acc, frX);                      // frX := h

        // ---- S2: Ahat = h @ W2^T + b2 + A ----
        init_from_res(sResW, lane, sBias, 2, t, acc);
        run_gemm(sFrag, 2, lane, frX, acc);
        acc_to_afrag(acc, frX);                      // frX := Ahat

        // ---- S3: h2 = relu(Ahat @ W3^T + b3) ----
        bias_init(sBias, 3, t, acc);
        run_gemm(sFrag, 3, lane, frX, acc);
        do_relu(acc);
        acc_to_afrag(acc, frX);                      // frX := h2

        // ---- S4: out = h2 @ W4^T + b4 + tf (tf fp16 from bounce) ----
        {
            const float2* bp = reinterpret_cast<const float2*>(sBias + 4 * DIM + 2 * t);
#pragma unroll
            for (int nb = 0; nb < 16; nb++) {
                float2 b = bp[nb * 4];
                unsigned u0 = *reinterpret_cast<unsigned*>(sIOW + io_off(g,     nb * 16 + 4 * t));
                unsigned u1 = *reinterpret_cast<unsigned*>(sIOW + io_off(g + 8, nb * 16 + 4 * t));
                float2 f0 = __half22float2(*reinterpret_cast<__half2*>(&u0));
                float2 f1 = __half22float2(*reinterpret_cast<__half2*>(&u1));
                acc[nb][0] = b.x + f0.x; acc[nb][1] = b.y + f0.y;
                acc[nb][2] = b.x + f1.x; acc[nb][3] = b.y + f1.y;
            }
        }
        run_gemm(sFrag, 4, lane, frX, acc);

        // ---- output: bounce as fp32 rows (8 rows x 512B per pass) ----
        // pass 0: rows base+0..7 (acc[..][0,1]); pass 1: rows base+8..15 ([2,3])
#pragma unroll
        for (int p = 0; p < 2; p++) {
            __syncwarp();
#pragma unroll
            for (int nb = 0; nb < 16; nb++)
                *reinterpret_cast<float2*>(
                    sIOW + g * 512 + ((nb * 32 + t * 8) ^ (g << 4))) =
                    make_float2(acc[nb][2 * p], acc[nb][2 * p + 1]);
            __syncwarp();
#pragma unroll
            for (int i = 0; i < 8; i++) {
                float4 w = *reinterpret_cast<float4*>(
                    sIOW + i * 512 + ((lane * 16) ^ (i << 4)));
                *reinterpret_cast<float4*>(
                    out + (size_t)(base + p * 8 + i) * DIM + lane * 4) = w;
            }
        }
    }
}

// ----------------------------------------------------------------------------
extern "C" void kernel_launch(void* const* d_in, const int* in_sizes, int n_in,
                              void* d_out, int out_size)
{
    const float* tf  = (const float*)d_in[0];
    const float* ipw = (const float*)d_in[1];
    const float* ipb = (const float*)d_in[2];
    const float* ow  = (const float*)d_in[3];
    const float* ob  = (const float*)d_in[4];
    const float* fw1 = (const float*)d_in[5];
    const float* fb1 = (const float*)d_in[6];
    const float* fw2 = (const float*)d_in[7];
    const float* fb2 = (const float*)d_in[8];
    const float* uw1 = (const float*)d_in[9];
    const float* ub1 = (const float*)d_in[10];
    const float* uw2 = (const float*)d_in[11];
    const float* ub2 = (const float*)d_in[12];

    precompute_pack<<<dim3(128, 5), 128>>>(ipw, ipb, ow, ob, fw1, fb1,
                                           fw2, fb2, uw1, ub1, uw2, ub2);

    cudaFuncSetAttribute(fused_kernel,
                         cudaFuncAttributeMaxDynamicSharedMemorySize, SMEM_TOTAL);
    fused_kernel<<<GRID_MAIN, THREADS, SMEM_TOTAL>>>(tf, (float*)d_out);
}

// round 17
// speedup vs baseline: 7.0601x; 1.0701x over previous
#include <cuda_runtime.h>
#include <cuda_fp16.h>
#include <cstdint>

// ============================================================================
// FeatureSharingLayer: 5 chained 128x128 GEMMs over M = 262144 rows.
// mma.sync m16n8k16 fp16 (fp32 accum), warp-independent 16-row blocks.
// R16: explicit register double-buffer on B fragments -- the full next-kb
// window (8x uint4) is batch-loaded before the current kb's 16 MMAs issue,
// so B LDS latency is covered by ~128 issue cycles of tensor work.
// (R7/R11/R15 all pinned at ~16 cyc/MMA with pipe-active 8 -> testing the
// exposed-LDS-latency hypothesis against a structural rt=16 floor.)
// ============================================================================

#define DIM 128
#define M_TOTAL (32768 * 8)        // 262144
#define N_BLK16 (M_TOTAL / 16)     // 16384
#define N_STAGES 5
#define GRID_MAIN 152
#define THREADS 256
#define N_WARPS (THREADS / 32)     // 8
#define STRIDE (GRID_MAIN * N_WARPS)

// packed B fragments: [stage][kb(8)][nbp(8)][lane(32)] -> uint4
__device__ uint4 g_fragB[N_STAGES * 8 * 8 * 32];
__device__ float g_bias[N_STAGES][DIM];

#define SMEM_FRAG_BYTES (N_STAGES * 8 * 8 * 32 * 16)       // 163840
#define SMEM_BIAS_OFF   SMEM_FRAG_BYTES
#define SMEM_BIAS_BYTES (N_STAGES * DIM * 4)               // 2560
#define SMEM_RESA_OFF   (SMEM_BIAS_OFF + SMEM_BIAS_BYTES)  // 166400
#define SMEM_RESA_BYTES (N_WARPS * 16 * 32 * 8)            // 32768
#define SMEM_TOTAL      (SMEM_RESA_OFF + SMEM_RESA_BYTES)  // 199168

// ----------------------------------------------------------------------------
// Prologue: fold weights, convert fp16, scatter into B-fragment layout.
// ----------------------------------------------------------------------------
__global__ void precompute_pack(
    const float* __restrict__ ipw, const float* __restrict__ ipb,
    const float* __restrict__ ow,  const float* __restrict__ ob,
    const float* __restrict__ fw1, const float* __restrict__ fb1,
    const float* __restrict__ fw2, const float* __restrict__ fb2,
    const float* __restrict__ uw1, const float* __restrict__ ub1,
    const float* __restrict__ uw2, const float* __restrict__ ub2)
{
    const int n = blockIdx.x, s = blockIdx.y, k = threadIdx.x;
    __shared__ float srow[DIM];

    float v = 0.f;
    if (s == 0) {
        srow[k] = ow[n * DIM + k];
        __syncthreads();
#pragma unroll 8
        for (int j = 0; j < DIM; j++)
            v += srow[j] * ipw[(256 + j) * DIM + k];
    } else if (s == 1) {
#pragma unroll
        for (int t = 0; t < 8; t++) v += fw1[n * 1024 + t * DIM + k];
    } else if (s == 2) v = fw2[n * DIM + k];
    else if (s == 3)   v = uw1[n * DIM + k];
    else               v = uw2[n * DIM + k];

    {
        const int lane = (n & 7) * 4 + ((k & 7) >> 1);
        const int idx4 = ((s * 8 + (k >> 4)) * 8 + (n >> 4)) * 32 + lane;
        const int slot = ((n >> 3) & 1) * 4 + ((k >> 3) & 1) * 2 + (k & 1);
        reinterpret_cast<__half*>(g_fragB)[idx4 * 8 + slot] = __float2half(v);
    }

    if (k == 0) {
        float b;
        if (s == 0) {
            b = ob[n];
            for (int j = 0; j < DIM; j++) b += ow[n * DIM + j] * ipb[256 + j];
        } else if (s == 1) b = fb1[n];
        else if (s == 2)   b = fb2[n];
        else if (s == 3)   b = ub1[n];
        else               b = ub2[n];
        g_bias[s][n] = b;
    }
}

// ----------------------------------------------------------------------------
// Device helpers
// ----------------------------------------------------------------------------
__device__ __forceinline__ unsigned pack_h2(float x, float y)
{
    __half2 h = __floats2half2_rn(x, y);
    return *reinterpret_cast<unsigned*>(&h);
}

__device__ __forceinline__ void mma16816(float c[4], const unsigned a[4],
                                         unsigned b0, unsigned b1)
{
    asm volatile(
        "mma.sync.aligned.m16n8k16.row.col.f32.f16.f16.f32 "
        "{%0,%1,%2,%3}, {%4,%5,%6,%7}, {%8,%9}, {%0,%1,%2,%3};\n"
        : "+f"(c[0]), "+f"(c[1]), "+f"(c[2]), "+f"(c[3])
        : "r"(a[0]), "r"(a[1]), "r"(a[2]), "r"(a[3]), "r"(b0), "r"(b1));
}

// full 16x128 x 128x128 GEMM; B double-buffered in registers:
// next kb's 8 uint4 are batch-loaded BEFORE current kb's 16 MMAs.
__device__ __forceinline__ void run_gemm(const uint4* __restrict__ sFrag, int s,
                                         int lane, const unsigned a[8][4],
                                         float c[16][4])
{
    const uint4* bp = sFrag + (s * 8 * 8) * 32 + lane;
    uint4 cur[8];
#pragma unroll
    for (int p = 0; p < 8; p++) cur[p] = bp[p * 32];

#pragma unroll
    for (int kb = 0; kb < 8; kb++) {
        uint4 nxt[8];
        if (kb < 7) {
            const uint4* bq = bp + (kb + 1) * 8 * 32;
#pragma unroll
            for (int p = 0; p < 8; p++) nxt[p] = bq[p * 32];
        }
#pragma unroll
        for (int p = 0; p < 8; p++) {
            mma16816(c[2 * p],     a[kb], cur[p].x, cur[p].y);
            mma16816(c[2 * p + 1], a[kb], cur[p].z, cur[p].w);
        }
        if (kb < 7) {
#pragma unroll
            for (int p = 0; p < 8; p++) cur[p] = nxt[p];
        }
    }
}

__device__ __forceinline__ void bias_init(const float* __restrict__ sb, int s,
                                          int t, float c[16][4])
{
    const float2* bp = reinterpret_cast<const float2*>(sb + s * DIM + 2 * t);
#pragma unroll
    for (int nb = 0; nb < 16; nb++) {
        float2 b = bp[nb * 4];
        c[nb][0] = b.x; c[nb][1] = b.y; c[nb][2] = b.x; c[nb][3] = b.y;
    }
}

__device__ __forceinline__ void do_relu(float c[16][4])
{
#pragma unroll
    for (int nb = 0; nb < 16; nb++) {
        c[nb][0] = fmaxf(c[nb][0], 0.f); c[nb][1] = fmaxf(c[nb][1], 0.f);
        c[nb][2] = fmaxf(c[nb][2], 0.f); c[nb][3] = fmaxf(c[nb][3], 0.f);
    }
}

__device__ __forceinline__ void acc_to_afrag(const float c[16][4], unsigned a[8][4])
{
#pragma unroll
    for (int kb = 0; kb < 8; kb++) {
        a[kb][0] = pack_h2(c[2 * kb][0],     c[2 * kb][1]);
        a[kb][1] = pack_h2(c[2 * kb][2],     c[2 * kb][3]);
        a[kb][2] = pack_h2(c[2 * kb + 1][0], c[2 * kb + 1][1]);
        a[kb][3] = pack_h2(c[2 * kb + 1][2], c[2 * kb + 1][3]);
    }
}

// warp-private fp16 residual-A in smem (fragment-native, conflict-free)
__device__ __forceinline__ void store_res(uint2* __restrict__ sResW, int lane,
                                          const float c[16][4])
{
    uint2* p = sResW + lane;
#pragma unroll
    for (int nb = 0; nb < 16; nb++)
        p[nb * 32] = make_uint2(pack_h2(c[nb][0], c[nb][1]),
                                pack_h2(c[nb][2], c[nb][3]));
}

__device__ __forceinline__ void init_from_res(const uint2* __restrict__ sResW,
                                              int lane,
                                              const float* __restrict__ sb, int s,
                                              int t, float c[16][4])
{
    const uint2* p = sResW + lane;
    const float2* bp = reinterpret_cast<const float2*>(sb + s * DIM + 2 * t);
#pragma unroll
    for (int nb = 0; nb < 16; nb++) {
        uint2 r = p[nb * 32];
        float2 b = bp[nb * 4];
        float2 f0 = __half22float2(*reinterpret_cast<__half2*>(&r.x));
        float2 f1 = __half22float2(*reinterpret_cast<__half2*>(&r.y));
        c[nb][0] = b.x + f0.x; c[nb][1] = b.y + f0.y;
        c[nb][2] = b.x + f1.x; c[nb][3] = b.y + f1.y;
    }
}

// ----------------------------------------------------------------------------
// Main fused kernel: persistent, warp-independent 16-row blocks.
// ----------------------------------------------------------------------------
__global__ void __launch_bounds__(THREADS, 1)
fused_kernel(const float* __restrict__ tf, float* __restrict__ out)
{
    extern __shared__ unsigned char smem[];
    uint4* sFrag = reinterpret_cast<uint4*>(smem);
    float* sBias = reinterpret_cast<float*>(smem + SMEM_BIAS_OFF);

    {   // one-time weight staging
        const uint4* src = g_fragB;
        for (int i = threadIdx.x; i < SMEM_FRAG_BYTES / 16; i += THREADS)
            sFrag[i] = src[i];
        const float* bs = &g_bias[0][0];
        for (int i = threadIdx.x; i < N_STAGES * DIM; i += THREADS)
            sBias[i] = bs[i];
    }
    __syncthreads();

    const int warp = threadIdx.x >> 5, lane = threadIdx.x & 31;
    const int g = lane >> 2, t = lane & 3;
    uint2* sResW = reinterpret_cast<uint2*>(smem + SMEM_RESA_OFF) + warp * 512;

#pragma unroll 1
    for (int blk = blockIdx.x * N_WARPS + warp; blk < N_BLK16; blk += STRIDE) {
        const int r0 = blk * 16 + g;                 // rows r0, r0+8
        const float* p0 = tf + (size_t)r0 * DIM;
        const float* p1 = p0 + 8 * DIM;

        // ---- stage-0 A fragments straight from gmem ----
        unsigned frX[8][4];
#pragma unroll
        for (int kb = 0; kb < 8; kb++) {
            float2 x0 = *reinterpret_cast<const float2*>(p0 + kb * 16 + 2 * t);
            float2 x1 = *reinterpret_cast<const float2*>(p1 + kb * 16 + 2 * t);
            float2 x2 = *reinterpret_cast<const float2*>(p0 + kb * 16 + 8 + 2 * t);
            float2 x3 = *reinterpret_cast<const float2*>(p1 + kb * 16 + 8 + 2 * t);
            frX[kb][0] = pack_h2(x0.x, x0.y);
            frX[kb][1] = pack_h2(x1.x, x1.y);
            frX[kb][2] = pack_h2(x2.x, x2.y);
            frX[kb][3] = pack_h2(x3.x, x3.y);
        }

        float acc[16][4];

        // ---- S0: A = tf @ Wc^T + bc ----
        bias_init(sBias, 0, t, acc);
        run_gemm(sFrag, 0, lane, frX, acc);
        store_res(sResW, lane, acc);                 // park A (fp16)
        acc_to_afrag(acc, frX);                      // frX := A

        // ---- S1: h = relu(A @ W1eff^T + b1) ----
        bias_init(sBias, 1, t, acc);
        run_gemm(sFrag, 1, lane, frX, acc);
        do_relu(acc);
        acc_to_afrag(acc, frX);                      // frX := h

        // ---- S2: Ahat = h @ W2^T + b2 + A ----
        init_from_res(sResW, lane, sBias, 2, t, acc);
        run_gemm(sFrag, 2, lane, frX, acc);
        acc_to_afrag(acc, frX);                      // frX := Ahat

        // ---- S3: h2 = relu(Ahat @ W3^T + b3) ----
        bias_init(sBias, 3, t, acc);
        run_gemm(sFrag, 3, lane, frX, acc);
        do_relu(acc);
        acc_to_afrag(acc, frX);                      // frX := h2

        // ---- S4: out = h2 @ W4^T + b4 + tf (exact fp32 residual) ----
        {
            const float2* bp = reinterpret_cast<const float2*>(sBias + 4 * DIM + 2 * t);
#pragma unroll
            for (int nb = 0; nb < 16; nb++) {
                float2 b  = bp[nb * 4];
                float2 q0 = *reinterpret_cast<const float2*>(p0 + nb * 8 + 2 * t);
                float2 q1 = *reinterpret_cast<const float2*>(p1 + nb * 8 + 2 * t);
                acc[nb][0] = q0.x + b.x; acc[nb][1] = q0.y + b.y;
                acc[nb][2] = q1.x + b.x; acc[nb][3] = q1.y + b.y;
            }
        }
        run_gemm(sFrag, 4, lane, frX, acc);

        // ---- store ----
        float* o0 = out + (size_t)r0 * DIM;
        float* o1 = o0 + 8 * DIM;
#pragma unroll
        for (int nb = 0; nb < 16; nb++) {
            *reinterpret_cast<float2*>(o0 + nb * 8 + 2 * t) =
                make_float2(acc[nb][0], acc[nb][1]);
            *reinterpret_cast<float2*>(o1 + nb * 8 + 2 * t) =
                make_float2(acc[nb][2], acc[nb][3]);
        }
    }
}

// ----------------------------------------------------------------------------
extern "C" void kernel_launch(void* const* d_in, const int* in_sizes, int n_in,
                              void* d_out, int out_size)
{
    const float* tf  = (const float*)d_in[0];
    const float* ipw = (const float*)d_in[1];
    const float* ipb = (const float*)d_in[2];
    const float* ow  = (const float*)d_in[3];
    const float* ob  = (const float*)d_in[4];
    const float* fw1 = (const float*)d_in[5];
    const float* fb1 = (const float*)d_in[6];
    const float* fw2 = (const float*)d_in[7];
    const float* fb2 = (const float*)d_in[8];
    const float* uw1 = (const float*)d_in[9];
    const float* ub1 = (const float*)d_in[10];
    const float* uw2 = (const float*)d_in[11];
    const float* ub2 = (const float*)d_in[12];

    precompute_pack<<<dim3(128, 5), 128>>>(ipw, ipb, ow, ob, fw1, fb1,
                                           fw2, fb2, uw1, ub1, uw2, ub2);

    cudaFuncSetAttribute(fused_kernel,
                         cudaFuncAttributeMaxDynamicSharedMemorySize, SMEM_TOTAL);
    fused_kernel<<<GRID_MAIN, THREADS, SMEM_TOTAL>>>(tf, (float*)d_out);
}